// round 1
// baseline (speedup 1.0000x reference)
#include <cuda_runtime.h>
#include <cstdint>

// Problem constants
#define T_ 2048
#define B_ 64
#define D_ 256
#define H_ 256
#define L_ 2
#define DH_ (D_ + H_)   // 512
#define M_ (T_ * B_)    // 131072 rows per layer GEMM

// Effective bias: bias_eff[l][b][g][h] = b[l,g,h] + sum_j h0[l,b,j] * W[l,g,D+j,h]
__device__ float g_bias[L_ * B_ * 4 * H_];   // 512 KB scratch (allowed: __device__ global)

// ---------------------------------------------------------------------------
// Kernel 1: effective bias (tiny GEMM, 33 MFLOP total)
// ---------------------------------------------------------------------------
__global__ void bias_kernel(const float* __restrict__ h0,
                            const float* __restrict__ W,
                            const float* __restrict__ bb)
{
    int idx = blockIdx.x * blockDim.x + threadIdx.x;   // ((l*B+b)*4+g)*H + h
    int h = idx & (H_ - 1);
    int g = (idx >> 8) & 3;
    int b = (idx >> 10) & (B_ - 1);
    int l = idx >> 16;

    const float* h0p = h0 + (l * B_ + b) * H_;
    const float* wp  = W + ((size_t)(l * 4 + g) * DH_ + D_) * H_ + h;
    float acc = bb[(l * 4 + g) * H_ + h];
#pragma unroll 8
    for (int j = 0; j < H_; j++)
        acc = fmaf(h0p[j], wp[(size_t)j * H_], acc);
    g_bias[idx] = acc;
}

// ---------------------------------------------------------------------------
// f32x2 helpers (packed dual-lane FP32 FMA — doubles FFMA throughput on sm_103a)
// ---------------------------------------------------------------------------
__device__ __forceinline__ unsigned long long ffma2(unsigned long long a,
                                                    unsigned long long b,
                                                    unsigned long long c)
{
    unsigned long long d;
    asm("fma.rn.f32x2 %0, %1, %2, %3;" : "=l"(d) : "l"(a), "l"(b), "l"(c));
    return d;
}
__device__ __forceinline__ unsigned long long pack2(float x)
{
    unsigned long long d;
    asm("mov.b64 %0, {%1, %1};" : "=l"(d) : "f"(x));
    return d;
}
__device__ __forceinline__ float lo32(unsigned long long v)
{
    return __uint_as_float((unsigned)(v & 0xffffffffull));
}
__device__ __forceinline__ float hi32(unsigned long long v)
{
    return __uint_as_float((unsigned)(v >> 32));
}

__device__ __forceinline__ float sigmoidf_(float x)
{
    // exp(-x)->inf for very negative x => 1/(1+inf)=0, correct limit.
    return __fdividef(1.0f, 1.0f + __expf(-x));
}
__device__ __forceinline__ float tanhf_(float x)
{
    // 1 - 2/(1+exp(2x)): exact limits at both ends, no inf/inf.
    return 1.0f - __fdividef(2.0f, 1.0f + __expf(2.0f * x));
}

// ---------------------------------------------------------------------------
// Kernel 2: fused GEMM (gates) + LSTM activations + output writes.
//   Tile: 64 rows (one full timestep: rows m0..m0+63 share t, b=0..63)
//         x 64 h-columns x 4 gates (N-tile = 256 gate-cols).
//   Per thread: 8 rows x 2 h x 4 gates, accumulated as 4 f32x2 pairs/row.
//   A row m address: base + (m>>6)*t_stride + (m&63)*256
//     layer 0: base=inputs, t_stride=B*D   ([T,B,D] contiguous)
//     layer 1: base=h_n,    t_stride=L*B*H (reads layer-0 h in place)
// ---------------------------------------------------------------------------
__global__ void __launch_bounds__(256, 2)
lstm_layer_kernel(const float* __restrict__ A, int t_stride,
                  const float* __restrict__ W,      // + l*4*DH*H (x-part first)
                  const float* __restrict__ c0,     // + l*B*H
                  int l,
                  float* __restrict__ hn,           // h_n base [T,L,B,H]
                  float* __restrict__ cn,           // c_n base [T,L,B,H]
                  float* __restrict__ x_out)        // final x (layer L-1 only), else null
{
    __shared__ __align__(16) float As[64][20];      // [row][k] (+pad)
    __shared__ __align__(16) float Bs[16][256];     // [k][h_local*4 + g]

    const int m0  = blockIdx.x * 64;
    const int h0b = blockIdx.y * 64;
    const int tid = threadIdx.x;
    const int rg  = tid >> 5;     // 0..7  (row group: rows rg*8..rg*8+7)
    const int cg  = tid & 31;     // 0..31 (h within half-tile)

    unsigned long long acc[8][4];
#pragma unroll
    for (int i = 0; i < 8; i++)
#pragma unroll
        for (int p = 0; p < 4; p++) acc[i][p] = 0ull;

    // A-load mapping: 256 threads load 64 rows x 16 k as float4
    const int ar = tid >> 2;          // 0..63
    const int aq = tid & 3;           // 0..3 -> k offset aq*4
    const int arow = m0 + ar;
    const float* aptr = A + (size_t)(arow >> 6) * t_stride + (arow & 63) * 256 + aq * 4;

    // B-load mapping: thread covers fixed (hl, g), all 16 k per tile
    const int hl = tid & 63;
    const int gg = tid >> 6;          // 0..3
    const float* wptr = W + (size_t)gg * DH_ * H_ + h0b + hl;

#pragma unroll 1
    for (int kt = 0; kt < 16; kt++) {
        float4 av = *(const float4*)(aptr + kt * 16);
        *(float4*)&As[ar][aq * 4] = av;
#pragma unroll
        for (int u = 0; u < 16; u++)
            Bs[u][hl * 4 + gg] = wptr[(size_t)(kt * 16 + u) * H_];
        __syncthreads();

#pragma unroll
        for (int k = 0; k < 16; k++) {
            ulonglong2 bA = *(const ulonglong2*)&Bs[k][cg * 4];
            ulonglong2 bB = *(const ulonglong2*)&Bs[k][(cg + 32) * 4];
#pragma unroll
            for (int i = 0; i < 8; i++) {
                unsigned long long pa = pack2(As[rg * 8 + i][k]);
                acc[i][0] = ffma2(pa, bA.x, acc[i][0]);
                acc[i][1] = ffma2(pa, bA.y, acc[i][1]);
                acc[i][2] = ffma2(pa, bB.x, acc[i][2]);
                acc[i][3] = ffma2(pa, bB.y, acc[i][3]);
            }
        }
        __syncthreads();
    }

    // Epilogue: bias + activations + writes
    const float* bias_l = g_bias + (size_t)l * B_ * 4 * H_;
    const float* c0_l   = c0 + (size_t)l * B_ * H_;
    float* hn_l = hn + (size_t)l * B_ * H_;
    float* cn_l = cn + (size_t)l * B_ * H_;

#pragma unroll
    for (int i = 0; i < 8; i++) {
        int row = m0 + rg * 8 + i;
        int t = row >> 6;
        int b = row & 63;
        const float* bp = bias_l + (size_t)b * 4 * H_;   // [g][h]
        const float* cp = c0_l + (size_t)b * H_;
        size_t obase = (size_t)t * (L_ * B_ * H_) + (size_t)b * H_;
#pragma unroll
        for (int hh = 0; hh < 2; hh++) {
            int h = h0b + cg + hh * 32;
            unsigned long long p01 = acc[i][hh * 2 + 0];
            unsigned long long p23 = acc[i][hh * 2 + 1];
            float gf = lo32(p01) + bp[0 * H_ + h];
            float gi = hi32(p01) + bp[1 * H_ + h];
            float gc = lo32(p23) + bp[2 * H_ + h];
            float go = hi32(p23) + bp[3 * H_ + h];
            float f  = sigmoidf_(gf);
            float ii = sigmoidf_(gi);
            float gt = tanhf_(gc);
            float o  = sigmoidf_(go);
            float c  = fmaf(f, cp[h], ii * gt);
            float hv = o * tanhf_(c);
            hn_l[obase + h] = hv;
            cn_l[obase + h] = c;
            if (x_out) x_out[(size_t)row * H_ + h] = hv;
        }
    }
}

// ---------------------------------------------------------------------------
// Launch: bias kernel, then one fused layer kernel per layer.
// Output layout: [ x (T*B*H) | h_n (T*L*B*H) | c_n (T*L*B*H) ]
// ---------------------------------------------------------------------------
extern "C" void kernel_launch(void* const* d_in, const int* in_sizes, int n_in,
                              void* d_out, int out_size)
{
    const float* inputs = (const float*)d_in[0];   // [T,B,D]
    const float* h0     = (const float*)d_in[1];   // [L,B,H]
    const float* c0     = (const float*)d_in[2];   // [L,B,H]
    const float* W      = (const float*)d_in[3];   // [L,4,D+H,H]
    const float* bb     = (const float*)d_in[4];   // [L,4,H]

    float* out  = (float*)d_out;
    float* x_out = out;
    float* hn   = out + (size_t)T_ * B_ * H_;
    float* cn   = hn + (size_t)T_ * L_ * B_ * H_;

    bias_kernel<<<(L_ * B_ * 4 * H_) / 256, 256>>>(h0, W, bb);

    dim3 grid(M_ / 64, H_ / 64);

    // Layer 0: A = inputs, writes h_n[:,0], c_n[:,0]
    lstm_layer_kernel<<<grid, 256>>>(inputs, B_ * D_,
                                     W, c0, 0, hn, cn, nullptr);

    // Layer 1: A = h_n[:,0] (in place), writes h_n[:,1], c_n[:,1], and x
    lstm_layer_kernel<<<grid, 256>>>(hn, L_ * B_ * H_,
                                     W + (size_t)4 * DH_ * H_, c0, 1, hn, cn, x_out);
}

// round 4
// speedup vs baseline: 1.7711x; 1.7711x over previous
#include <cuda_runtime.h>
#include <cuda_bf16.h>
#include <cstdint>

// Problem constants
#define T_ 2048
#define B_ 64
#define D_ 256
#define H_ 256
#define L_ 2
#define M_ (T_ * B_)       // 131072 GEMM rows per layer

// W image: per (l, ntile 0..3): 8 blocks (0-3 = W_hi k-chunks, 4-7 = W_lo),
// each block 256 n-rows x 64 k bf16 = 32KB, rows 128B, XOR-swizzled.
__device__ __align__(16) unsigned char g_W[(size_t)L_ * 4 * 8 * 32768]; // 2 MB
__device__ __align__(16) float4 g_bias4[(size_t)L_ * B_ * H_];          // [l][b][h].(f,i,g,o)

// ---------------------------------------------------------------------------
// helpers
// ---------------------------------------------------------------------------
__device__ __forceinline__ uint32_t smem_u32(const void* p)
{
    uint32_t a;
    asm("{ .reg .u64 t; cvta.to.shared.u64 t, %1; cvt.u32.u64 %0, t; }" : "=r"(a) : "l"(p));
    return a;
}
__device__ __forceinline__ unsigned short bf16_bits(__nv_bfloat16 v)
{
    return *reinterpret_cast<unsigned short*>(&v);
}
__device__ __forceinline__ float sigmoidf_(float x)
{
    return __fdividef(1.0f, 1.0f + __expf(-x));
}
__device__ __forceinline__ float tanhf_(float x)
{
    return 1.0f - __fdividef(2.0f, 1.0f + __expf(2.0f * x));
}

#define CP16(s, g) asm volatile("cp.async.cg.shared.global [%0], [%1], 16;" :: "r"(s), "l"(g))
#define CP_COMMIT() asm volatile("cp.async.commit_group;" ::: "memory")
#define CP_WAIT1() asm volatile("cp.async.wait_group 1;" ::: "memory")
#define CP_WAIT0() asm volatile("cp.async.wait_group 0;" ::: "memory")

#define LDSM4(r, addr) asm volatile( \
    "ldmatrix.sync.aligned.m8n8.x4.shared.b16 {%0,%1,%2,%3}, [%4];" \
    : "=r"((r)[0]), "=r"((r)[1]), "=r"((r)[2]), "=r"((r)[3]) : "r"(addr))

#define MMA(d, a, b0, b1) asm volatile( \
    "mma.sync.aligned.m16n8k16.row.col.f32.bf16.bf16.f32 " \
    "{%0,%1,%2,%3},{%4,%5,%6,%7},{%8,%9},{%0,%1,%2,%3};" \
    : "+f"((d)[0]), "+f"((d)[1]), "+f"((d)[2]), "+f"((d)[3]) \
    : "r"((a)[0]), "r"((a)[1]), "r"((a)[2]), "r"((a)[3]), "r"(b0), "r"(b1))

// ---------------------------------------------------------------------------
// Kernel 1: W -> bf16 hi/lo image, swizzled blocks (n = h*4+g gate interleave)
//   thread: one 16B unit = 8 k-values of one n.
// ---------------------------------------------------------------------------
__global__ void __launch_bounds__(256) wprep_kernel(const float* __restrict__ W)
{
    int idx = blockIdx.x * 256 + threadIdx.x;     // 131072 total
    int nloc = idx & 255;
    int j = (idx >> 8) & 7;
    int rest = idx >> 11;                          // ((l*4+nt)*8 + blk), 0..63
    int blk = rest & 7;
    int nt = (rest >> 3) & 3;
    int l = rest >> 5;
    int hl = blk >> 2, kb = blk & 3;
    int n = nt * 256 + nloc, g = n & 3, h = n >> 2;
    int k0 = kb * 64 + j * 8;

    const float* wp = W + ((size_t)(l * 4 + g) * 512 + k0) * 256 + h;
    unsigned short v[8];
#pragma unroll
    for (int i = 0; i < 8; i++) {
        float w = wp[(size_t)i * 256];
        __nv_bfloat16 e = __float2bfloat16(w);
        if (hl)
            e = __float2bfloat16(w - __bfloat162float(e));
        v[i] = bf16_bits(e);
    }
    uint4 out;
    out.x = (uint32_t)v[0] | ((uint32_t)v[1] << 16);
    out.y = (uint32_t)v[2] | ((uint32_t)v[3] << 16);
    out.z = (uint32_t)v[4] | ((uint32_t)v[5] << 16);
    out.w = (uint32_t)v[6] | ((uint32_t)v[7] << 16);
    unsigned off = (unsigned)nloc * 128 + (((unsigned)j ^ ((unsigned)nloc & 7)) << 4);
    *(uint4*)(g_W + (size_t)rest * 32768 + off) = out;
}

// ---------------------------------------------------------------------------
// Kernel 2: effective bias (exact fp32): b[l,g,h] + sum_j h0[l,b,j]*W[l,g,D+j,h]
//   layout float4 [l][b][h] = (f,i,g,o)
// ---------------------------------------------------------------------------
__global__ void __launch_bounds__(256) bias_kernel(const float* __restrict__ h0,
                                                   const float* __restrict__ W,
                                                   const float* __restrict__ bb)
{
    int idx = blockIdx.x * 256 + threadIdx.x;      // 131072
    int g = idx & 3;
    int h = (idx >> 2) & 255;
    int b = (idx >> 10) & 63;
    int l = idx >> 16;

    const float* h0p = h0 + (l * B_ + b) * H_;
    const float* wp  = W + ((size_t)(l * 4 + g) * 512 + 256) * 256 + h;
    float acc = bb[(l * 4 + g) * H_ + h];
#pragma unroll 8
    for (int j = 0; j < H_; j++)
        acc = fmaf(h0p[j], wp[(size_t)j * 256], acc);
    ((float*)g_bias4)[idx] = acc;
}

// ---------------------------------------------------------------------------
// Kernel 3: HMMA GEMM (3-term bf16 split) + fused LSTM epilogue.
//   CTA: 128m x 256n, 8 warps (2m x 4n grid), warp tile 64x64.
//   smem: A-hi/lo resident (128KB: [hl][kb 0..3][m row 128B swz]),
//         B double buffer 2x32KB.
//   grid: x = n-tile 0..3 (64 h each), y = m-tile 0..1023.
// ---------------------------------------------------------------------------
#define SM_B 131072u
#define SMEM_SZ 196608

__global__ void __launch_bounds__(256, 1)
gemm_kernel(const float* __restrict__ A, int t_stride,
            const float* __restrict__ c0, int l,
            float* __restrict__ hn, float* __restrict__ cn,
            float* __restrict__ x_out)
{
    extern __shared__ __align__(1024) unsigned char smem[];
    const int tid = threadIdx.x;
    const int bx = blockIdx.x;
    const int m0 = blockIdx.y * 128;
    const uint32_t su = smem_u32(smem);
    const int lane = tid & 31, wid = tid >> 5;
    const int wm = wid >> 2, wn = wid & 3;

    const unsigned char* gW = g_W + (size_t)(l * 4 + bx) * 8 * 32768;

    // --- issue B chunk 0,1 copies first (overlap with A conversion) ---
    {
        int bsel0 = 0, bsel1 = 1;                 // chunks 0,1 -> hi blocks 0,1
        const unsigned char* s0 = gW + (size_t)bsel0 * 32768 + tid * 16;
        const unsigned char* s1 = gW + (size_t)bsel1 * 32768 + tid * 16;
        uint32_t d0 = su + SM_B + tid * 16;
        uint32_t d1 = su + SM_B + 32768u + tid * 16;
#pragma unroll
        for (int j = 0; j < 8; j++) CP16(d0 + j * 4096, s0 + (size_t)j * 4096);
        CP_COMMIT();
#pragma unroll
        for (int j = 0; j < 8; j++) CP16(d1 + j * 4096, s1 + (size_t)j * 4096);
        CP_COMMIT();
    }

    // --- A load (fp32) + bf16 hi/lo split into resident smem ---
#pragma unroll
    for (int u = 0; u < 16; u++) {
        int idx = u * 256 + tid;                  // 4096 = 128 m x 32 k8
        int mloc = idx >> 5, k8 = idx & 31;
        int m = m0 + mloc;
        const float* gp = A + (size_t)(m >> 6) * t_stride + (size_t)(m & 63) * 256 + k8 * 8;
        float4 va = *(const float4*)gp;
        float4 vb = *(const float4*)(gp + 4);
        float v[8] = { va.x, va.y, va.z, va.w, vb.x, vb.y, vb.z, vb.w };
        uint32_t hi[4], lo[4];
#pragma unroll
        for (int p = 0; p < 4; p++) {
            __nv_bfloat16 e0 = __float2bfloat16(v[2 * p]);
            __nv_bfloat16 e1 = __float2bfloat16(v[2 * p + 1]);
            __nv_bfloat16 r0 = __float2bfloat16(v[2 * p] - __bfloat162float(e0));
            __nv_bfloat16 r1 = __float2bfloat16(v[2 * p + 1] - __bfloat162float(e1));
            hi[p] = (uint32_t)bf16_bits(e0) | ((uint32_t)bf16_bits(e1) << 16);
            lo[p] = (uint32_t)bf16_bits(r0) | ((uint32_t)bf16_bits(r1) << 16);
        }
        int kb = k8 >> 3, j = k8 & 7;
        unsigned off = (unsigned)kb * 16384u + (unsigned)mloc * 128u +
                       (((unsigned)j ^ ((unsigned)mloc & 7)) << 4);
        *(uint4*)(smem + off) = make_uint4(hi[0], hi[1], hi[2], hi[3]);
        *(uint4*)(smem + 65536u + off) = make_uint4(lo[0], lo[1], lo[2], lo[3]);
    }

    // --- per-lane ldmatrix offsets ---
    uint32_t aoff[4], aswz[4], boff[4], bswz[4];
    const uint32_t ua = (uint32_t)(lane >> 4);
    const uint32_t ub = (uint32_t)((lane >> 3) & 1);
#pragma unroll
    for (int tm = 0; tm < 4; tm++) {
        uint32_t row = (uint32_t)(wm * 64 + tm * 16 + (lane & 15));
        aoff[tm] = row * 128u;
        aswz[tm] = row & 7u;
    }
#pragma unroll
    for (int tn = 0; tn < 4; tn++) {
        uint32_t row = (uint32_t)(wn * 64 + tn * 16 + (lane & 7) + ((lane >> 4) << 3));
        boff[tn] = row * 128u;
        bswz[tn] = row & 7u;
    }

    float acc[4][8][4];
#pragma unroll
    for (int i = 0; i < 4; i++)
#pragma unroll
        for (int j = 0; j < 8; j++)
#pragma unroll
            for (int q = 0; q < 4; q++) acc[i][j][q] = 0.0f;

    // --- mainloop: 12 chunks (K' = 768) ---
#pragma unroll 1
    for (int c = 0; c < 12; c++) {
        const int buf = c & 1;
        if (c == 11) { CP_WAIT0(); } else { CP_WAIT1(); }
        __syncthreads();

        const uint32_t abase = su + ((c >> 2) == 1 ? 65536u : 0u) + (uint32_t)(c & 3) * 16384u;
        const uint32_t bbase = su + SM_B + (uint32_t)buf * 32768u;

#pragma unroll
        for (int ks = 0; ks < 4; ks++) {
            uint32_t a[4][4], bbf[4][4];
#pragma unroll
            for (int tm = 0; tm < 4; tm++)
                LDSM4(a[tm], abase + aoff[tm] +
                              ((((uint32_t)(ks * 2) + ua) ^ aswz[tm]) << 4));
#pragma unroll
            for (int tn = 0; tn < 4; tn++)
                LDSM4(bbf[tn], bbase + boff[tn] +
                               ((((uint32_t)(ks * 2) + ub) ^ bswz[tn]) << 4));
#pragma unroll
            for (int tm = 0; tm < 4; tm++)
#pragma unroll
                for (int tn = 0; tn < 4; tn++) {
                    MMA(acc[tm][tn * 2 + 0], a[tm], bbf[tn][0], bbf[tn][1]);
                    MMA(acc[tm][tn * 2 + 1], a[tm], bbf[tn][2], bbf[tn][3]);
                }
        }
        __syncthreads();

        if (c + 2 < 12) {
            int cn2 = c + 2;
            int bsel = (cn2 >= 8) ? 4 + (cn2 & 3) : (cn2 & 3);
            const unsigned char* s = gW + (size_t)bsel * 32768 + tid * 16;
            uint32_t d = su + SM_B + (uint32_t)buf * 32768u + tid * 16;
#pragma unroll
            for (int j = 0; j < 8; j++) CP16(d + j * 4096, s + (size_t)j * 4096);
            CP_COMMIT();
        }
    }

    // --- stage accumulators to smem (row pad 268 floats) ---
    {
        float* stage = (float*)smem;
        const int r0 = lane >> 2, cp2 = (lane & 3) * 2;
#pragma unroll
        for (int tm = 0; tm < 4; tm++) {
            int mr = wm * 64 + tm * 16 + r0;
#pragma unroll
            for (int j = 0; j < 8; j++) {
                int nc = wn * 64 + j * 8 + cp2;
                stage[(size_t)mr * 268 + nc]           = acc[tm][j][0];
                stage[(size_t)mr * 268 + nc + 1]       = acc[tm][j][1];
                stage[(size_t)(mr + 8) * 268 + nc]     = acc[tm][j][2];
                stage[(size_t)(mr + 8) * 268 + nc + 1] = acc[tm][j][3];
            }
        }
    }
    __syncthreads();

    // --- fused LSTM epilogue ---
    {
        const float* stage = (const float*)smem;
#pragma unroll 1
        for (int u = 0; u < 32; u++) {
            int idx = u * 256 + tid;
            int hloc = idx & 63, mloc = idx >> 6;
            int m = m0 + mloc;
            int t = m >> 6, b = m & 63;
            int hg = bx * 64 + hloc;

            float4 pre = *(const float4*)&stage[(size_t)mloc * 268 + hloc * 4];
            float4 bv = g_bias4[(size_t)(l * B_ + b) * H_ + hg];
            float f  = sigmoidf_(pre.x + bv.x);
            float ii = sigmoidf_(pre.y + bv.y);
            float gt = tanhf_(pre.z + bv.z);
            float o  = sigmoidf_(pre.w + bv.w);
            float c0v = c0[((size_t)l * B_ + b) * H_ + hg];
            float cc = fmaf(f, c0v, ii * gt);
            float hv = o * tanhf_(cc);

            size_t ob = (size_t)t * (L_ * B_ * H_) + (size_t)l * (B_ * H_) + (size_t)b * H_ + hg;
            hn[ob] = hv;
            cn[ob] = cc;
            if (x_out) x_out[(size_t)m * H_ + hg] = hv;
        }
    }
}

// ---------------------------------------------------------------------------
// Launch. Output layout: [ x (T*B*H) | h_n (T*L*B*H) | c_n (T*L*B*H) ]
// ---------------------------------------------------------------------------
extern "C" void kernel_launch(void* const* d_in, const int* in_sizes, int n_in,
                              void* d_out, int out_size)
{
    const float* inputs = (const float*)d_in[0];   // [T,B,D]
    const float* h0     = (const float*)d_in[1];   // [L,B,H]
    const float* c0     = (const float*)d_in[2];   // [L,B,H]
    const float* W      = (const float*)d_in[3];   // [L,4,D+H,H]
    const float* bb     = (const float*)d_in[4];   // [L,4,H]

    float* out   = (float*)d_out;
    float* x_out = out;
    float* hn    = out + (size_t)T_ * B_ * H_;
    float* cn    = hn + (size_t)T_ * L_ * B_ * H_;

    cudaFuncSetAttribute(gemm_kernel,
                         cudaFuncAttributeMaxDynamicSharedMemorySize, SMEM_SZ);

    wprep_kernel<<<512, 256>>>(W);
    bias_kernel<<<512, 256>>>(h0, W, bb);

    dim3 grid(4, M_ / 128);
    gemm_kernel<<<grid, 256, SMEM_SZ>>>(inputs, B_ * D_, c0, 0, hn, cn, nullptr);
    gemm_kernel<<<grid, 256, SMEM_SZ>>>(hn, L_ * B_ * H_, c0, 1, hn, cn, x_out);
}

// round 5
// speedup vs baseline: 1.8404x; 1.0391x over previous
#include <cuda_runtime.h>
#include <cuda_bf16.h>
#include <cstdint>

// Problem constants
#define T_ 2048
#define B_ 64
#define D_ 256
#define H_ 256
#define L_ 2
#define M_ (T_ * B_)       // 131072 GEMM rows per layer

// W image: per (l, ntile 0..3): 8 blocks (0-3 = W_hi k-chunks, 4-7 = W_lo),
// each block 256 n-rows x 64 k bf16 = 32KB, rows 128B, XOR-swizzled.
__device__ __align__(16) unsigned char g_W[(size_t)L_ * 4 * 8 * 32768]; // 2 MB
// A image: per m-tile (128 rows): [hi kb0..3 | lo kb0..3], 8 x 16KB = 128KB.
// Block: 128 m-rows x 64 k bf16, row 128B, unit swz = ((j ^ (mloc&7))<<4).
__device__ __align__(16) unsigned char g_A[(size_t)(M_ / 128) * 131072]; // 134 MB
__device__ __align__(16) float4 g_bias4[(size_t)L_ * B_ * H_];          // [l][b][h].(f,i,g,o)

// ---------------------------------------------------------------------------
// helpers
// ---------------------------------------------------------------------------
__device__ __forceinline__ uint32_t smem_u32(const void* p)
{
    uint32_t a;
    asm("{ .reg .u64 t; cvta.to.shared.u64 t, %1; cvt.u32.u64 %0, t; }" : "=r"(a) : "l"(p));
    return a;
}
__device__ __forceinline__ unsigned short bf16_bits(__nv_bfloat16 v)
{
    return *reinterpret_cast<unsigned short*>(&v);
}
__device__ __forceinline__ float sigmoidf_(float x)
{
    return __fdividef(1.0f, 1.0f + __expf(-x));
}
__device__ __forceinline__ float tanhf_(float x)
{
    return 1.0f - __fdividef(2.0f, 1.0f + __expf(2.0f * x));
}

#define CP16(s, g) asm volatile("cp.async.cg.shared.global [%0], [%1], 16;" :: "r"(s), "l"(g))
#define CP_COMMIT() asm volatile("cp.async.commit_group;" ::: "memory")
#define CP_WAIT1() asm volatile("cp.async.wait_group 1;" ::: "memory")
#define CP_WAIT0() asm volatile("cp.async.wait_group 0;" ::: "memory")

#define LDSM4(r, addr) asm volatile( \
    "ldmatrix.sync.aligned.m8n8.x4.shared.b16 {%0,%1,%2,%3}, [%4];" \
    : "=r"((r)[0]), "=r"((r)[1]), "=r"((r)[2]), "=r"((r)[3]) : "r"(addr))

#define MMA(d, a, b0, b1) asm volatile( \
    "mma.sync.aligned.m16n8k16.row.col.f32.bf16.bf16.f32 " \
    "{%0,%1,%2,%3},{%4,%5,%6,%7},{%8,%9},{%0,%1,%2,%3};" \
    : "+f"((d)[0]), "+f"((d)[1]), "+f"((d)[2]), "+f"((d)[3]) \
    : "r"((a)[0]), "r"((a)[1]), "r"((a)[2]), "r"((a)[3]), "r"(b0), "r"(b1))

// ---------------------------------------------------------------------------
// Kernel 1: W -> bf16 hi/lo image, swizzled blocks (n = h*4+g gate interleave)
// ---------------------------------------------------------------------------
__global__ void __launch_bounds__(256) wprep_kernel(const float* __restrict__ W)
{
    int idx = blockIdx.x * 256 + threadIdx.x;     // 131072 total
    int nloc = idx & 255;
    int j = (idx >> 8) & 7;
    int rest = idx >> 11;                          // ((l*4+nt)*8 + blk), 0..63
    int blk = rest & 7;
    int nt = (rest >> 3) & 3;
    int l = rest >> 5;
    int hl = blk >> 2, kb = blk & 3;
    int n = nt * 256 + nloc, g = n & 3, h = n >> 2;
    int k0 = kb * 64 + j * 8;

    const float* wp = W + ((size_t)(l * 4 + g) * 512 + k0) * 256 + h;
    unsigned short v[8];
#pragma unroll
    for (int i = 0; i < 8; i++) {
        float w = wp[(size_t)i * 256];
        __nv_bfloat16 e = __float2bfloat16(w);
        if (hl)
            e = __float2bfloat16(w - __bfloat162float(e));
        v[i] = bf16_bits(e);
    }
    uint4 out;
    out.x = (uint32_t)v[0] | ((uint32_t)v[1] << 16);
    out.y = (uint32_t)v[2] | ((uint32_t)v[3] << 16);
    out.z = (uint32_t)v[4] | ((uint32_t)v[5] << 16);
    out.w = (uint32_t)v[6] | ((uint32_t)v[7] << 16);
    unsigned off = (unsigned)nloc * 128 + (((unsigned)j ^ ((unsigned)nloc & 7)) << 4);
    *(uint4*)(g_W + (size_t)rest * 32768 + off) = out;
}

// ---------------------------------------------------------------------------
// Kernel 2: A(fp32) -> bf16 hi/lo swizzled image g_A.
//   thread: one 16B unit = 8 k of one row. Row m: (m>>6)*t_stride + (m&63)*256.
// ---------------------------------------------------------------------------
__global__ void __launch_bounds__(256) aprep_kernel(const float* __restrict__ A, int t_stride)
{
    int idx = blockIdx.x * 256 + threadIdx.x;      // 4,194,304
    int k8 = idx & 31;
    int m = idx >> 5;

    const float* gp = A + (size_t)(m >> 6) * t_stride + (size_t)(m & 63) * 256 + k8 * 8;
    float4 va = *(const float4*)gp;
    float4 vb = *(const float4*)(gp + 4);
    float v[8] = { va.x, va.y, va.z, va.w, vb.x, vb.y, vb.z, vb.w };
    uint32_t hi[4], lo[4];
#pragma unroll
    for (int p = 0; p < 4; p++) {
        __nv_bfloat16 e0 = __float2bfloat16(v[2 * p]);
        __nv_bfloat16 e1 = __float2bfloat16(v[2 * p + 1]);
        __nv_bfloat16 r0 = __float2bfloat16(v[2 * p] - __bfloat162float(e0));
        __nv_bfloat16 r1 = __float2bfloat16(v[2 * p + 1] - __bfloat162float(e1));
        hi[p] = (uint32_t)bf16_bits(e0) | ((uint32_t)bf16_bits(e1) << 16);
        lo[p] = (uint32_t)bf16_bits(r0) | ((uint32_t)bf16_bits(r1) << 16);
    }
    int mt = m >> 7, mloc = m & 127, kb = k8 >> 3, j = k8 & 7;
    size_t base = (size_t)mt * 131072 + (size_t)kb * 16384 + (size_t)mloc * 128 +
                  (((unsigned)j ^ ((unsigned)mloc & 7)) << 4);
    *(uint4*)(g_A + base) = make_uint4(hi[0], hi[1], hi[2], hi[3]);
    *(uint4*)(g_A + base + 65536) = make_uint4(lo[0], lo[1], lo[2], lo[3]);
}

// ---------------------------------------------------------------------------
// Kernel 3: effective bias (exact fp32): b[l,g,h] + sum_j h0[l,b,j]*W[l,g,D+j,h]
// ---------------------------------------------------------------------------
__global__ void __launch_bounds__(256) bias_kernel(const float* __restrict__ h0,
                                                   const float* __restrict__ W,
                                                   const float* __restrict__ bb)
{
    int idx = blockIdx.x * 256 + threadIdx.x;      // 131072
    int g = idx & 3;
    int h = (idx >> 2) & 255;
    int b = (idx >> 10) & 63;
    int l = idx >> 16;

    const float* h0p = h0 + (l * B_ + b) * H_;
    const float* wp  = W + ((size_t)(l * 4 + g) * 512 + 256) * 256 + h;
    float acc = bb[(l * 4 + g) * H_ + h];
#pragma unroll 8
    for (int j = 0; j < H_; j++)
        acc = fmaf(h0p[j], wp[(size_t)j * 256], acc);
    ((float*)g_bias4)[idx] = acc;
}

// ---------------------------------------------------------------------------
// Kernel 4: HMMA GEMM (3-term bf16 split) + fused LSTM epilogue.
//   CTA: 128m x 256n, 8 warps (2m x 4n), warp tile 64x64.
//   Both A and B streamed via cp.async; chunk buf = [A 16KB | B 32KB],
//   3 buffers, single __syncthreads per chunk, lookahead 2.
//   Chunk c: s=c>>2 (term), kb=c&3. Terms: [Ah*Wh][Al*Wh][Ah*Wl].
// ---------------------------------------------------------------------------
#define CHUNK_BYTES 49152u
#define SMEM_SZ 147456

__global__ void __launch_bounds__(256, 1)
gemm_kernel(const float* __restrict__ c0, int l,
            float* __restrict__ hn, float* __restrict__ cn,
            float* __restrict__ x_out)
{
    extern __shared__ __align__(1024) unsigned char smem[];
    const int tid = threadIdx.x;
    const int bx = blockIdx.x;
    const int by = blockIdx.y;
    const int m0 = by * 128;
    const uint32_t su = smem_u32(smem);
    const int lane = tid & 31, wid = tid >> 5;
    const int wm = wid >> 2, wn = wid & 3;

    const unsigned char* gWb = g_W + (size_t)(l * 4 + bx) * 262144;
    const unsigned char* gAb = g_A + (size_t)by * 131072;

    // chunk copy: A (4 units) + B (8 units) per thread
#define ISSUE_CHUNK(c, buf)                                                     \
    do {                                                                        \
        int s_ = (c) >> 2, kb_ = (c) & 3;                                       \
        const unsigned char* sa = gAb + (s_ == 1 ? 65536 : 0) + kb_ * 16384 + tid * 16; \
        const unsigned char* sb = gWb + (size_t)(s_ == 2 ? 4 + kb_ : kb_) * 32768 + tid * 16; \
        uint32_t da = su + (buf) * CHUNK_BYTES + tid * 16;                      \
        uint32_t db = da + 16384u;                                              \
        CP16(da, sa); CP16(da + 4096, sa + 4096);                               \
        CP16(da + 8192, sa + 8192); CP16(da + 12288, sa + 12288);               \
        CP16(db, sb); CP16(db + 4096, sb + 4096);                               \
        CP16(db + 8192, sb + 8192); CP16(db + 12288, sb + 12288);               \
        CP16(db + 16384, sb + 16384); CP16(db + 20480, sb + 20480);             \
        CP16(db + 24576, sb + 24576); CP16(db + 28672, sb + 28672);             \
        CP_COMMIT();                                                            \
    } while (0)

    // prologue: prefill chunks 0, 1
    ISSUE_CHUNK(0, 0);
    ISSUE_CHUNK(1, 1);

    // per-lane ldmatrix offsets
    uint32_t aoff[4], aswz[4], boff[4], bswz[4];
    const uint32_t ua = (uint32_t)(lane >> 4);
    const uint32_t ub = (uint32_t)((lane >> 3) & 1);
#pragma unroll
    for (int tm = 0; tm < 4; tm++) {
        uint32_t row = (uint32_t)(wm * 64 + tm * 16 + (lane & 15));
        aoff[tm] = row * 128u;
        aswz[tm] = row & 7u;
    }
#pragma unroll
    for (int tn = 0; tn < 4; tn++) {
        uint32_t row = (uint32_t)(wn * 64 + tn * 16 + (lane & 7) + ((lane >> 4) << 3));
        boff[tn] = row * 128u;
        bswz[tn] = row & 7u;
    }

    float acc[4][8][4];
#pragma unroll
    for (int i = 0; i < 4; i++)
#pragma unroll
        for (int j = 0; j < 8; j++)
#pragma unroll
            for (int q = 0; q < 4; q++) acc[i][j][q] = 0.0f;

    // mainloop: 12 chunks (K' = 768), single sync per chunk
#pragma unroll 1
    for (int c = 0; c < 12; c++) {
        const int buf = c - (c / 3) * 3;          // c % 3
        if (c == 11) { CP_WAIT0(); } else { CP_WAIT1(); }
        __syncthreads();

        if (c + 2 < 12) {
            int cn2 = c + 2;
            int bufn = cn2 - (cn2 / 3) * 3;
            ISSUE_CHUNK(cn2, bufn);
        }

        const uint32_t abase = su + (uint32_t)buf * CHUNK_BYTES;
        const uint32_t bbase = abase + 16384u;

#pragma unroll
        for (int ks = 0; ks < 4; ks++) {
            uint32_t a[4][4], bbf[4][4];
#pragma unroll
            for (int tm = 0; tm < 4; tm++)
                LDSM4(a[tm], abase + aoff[tm] +
                              ((((uint32_t)(ks * 2) + ua) ^ aswz[tm]) << 4));
#pragma unroll
            for (int tn = 0; tn < 4; tn++)
                LDSM4(bbf[tn], bbase + boff[tn] +
                               ((((uint32_t)(ks * 2) + ub) ^ bswz[tn]) << 4));
#pragma unroll
            for (int tm = 0; tm < 4; tm++)
#pragma unroll
                for (int tn = 0; tn < 4; tn++) {
                    MMA(acc[tm][tn * 2 + 0], a[tm], bbf[tn][0], bbf[tn][1]);
                    MMA(acc[tm][tn * 2 + 1], a[tm], bbf[tn][2], bbf[tn][3]);
                }
        }
    }
    __syncthreads();

    // stage accumulators to smem (row pad 268 floats)
    {
        float* stage = (float*)smem;
        const int r0 = lane >> 2, cp2 = (lane & 3) * 2;
#pragma unroll
        for (int tm = 0; tm < 4; tm++) {
            int mr = wm * 64 + tm * 16 + r0;
#pragma unroll
            for (int j = 0; j < 8; j++) {
                int nc = wn * 64 + j * 8 + cp2;
                stage[(size_t)mr * 268 + nc]           = acc[tm][j][0];
                stage[(size_t)mr * 268 + nc + 1]       = acc[tm][j][1];
                stage[(size_t)(mr + 8) * 268 + nc]     = acc[tm][j][2];
                stage[(size_t)(mr + 8) * 268 + nc + 1] = acc[tm][j][3];
            }
        }
    }
    __syncthreads();

    // fused LSTM epilogue
    {
        const float* stage = (const float*)smem;
#pragma unroll 1
        for (int u = 0; u < 32; u++) {
            int idx = u * 256 + tid;
            int hloc = idx & 63, mloc = idx >> 6;
            int m = m0 + mloc;
            int t = m >> 6, b = m & 63;
            int hg = bx * 64 + hloc;

            float4 pre = *(const float4*)&stage[(size_t)mloc * 268 + hloc * 4];
            float4 bv = g_bias4[(size_t)(l * B_ + b) * H_ + hg];
            float f  = sigmoidf_(pre.x + bv.x);
            float ii = sigmoidf_(pre.y + bv.y);
            float gt = tanhf_(pre.z + bv.z);
            float o  = sigmoidf_(pre.w + bv.w);
            float c0v = c0[((size_t)l * B_ + b) * H_ + hg];
            float cc = fmaf(f, c0v, ii * gt);
            float hv = o * tanhf_(cc);

            size_t ob = (size_t)t * (L_ * B_ * H_) + (size_t)l * (B_ * H_) + (size_t)b * H_ + hg;
            hn[ob] = hv;
            cn[ob] = cc;
            if (x_out) x_out[(size_t)m * H_ + hg] = hv;
        }
    }
#undef ISSUE_CHUNK
}

// ---------------------------------------------------------------------------
// Launch. Output layout: [ x (T*B*H) | h_n (T*L*B*H) | c_n (T*L*B*H) ]
// ---------------------------------------------------------------------------
extern "C" void kernel_launch(void* const* d_in, const int* in_sizes, int n_in,
                              void* d_out, int out_size)
{
    const float* inputs = (const float*)d_in[0];   // [T,B,D]
    const float* h0     = (const float*)d_in[1];   // [L,B,H]
    const float* c0     = (const float*)d_in[2];   // [L,B,H]
    const float* W      = (const float*)d_in[3];   // [L,4,D+H,H]
    const float* bb     = (const float*)d_in[4];   // [L,4,H]

    float* out   = (float*)d_out;
    float* x_out = out;
    float* hn    = out + (size_t)T_ * B_ * H_;
    float* cn    = hn + (size_t)T_ * L_ * B_ * H_;

    cudaFuncSetAttribute(gemm_kernel,
                         cudaFuncAttributeMaxDynamicSharedMemorySize, SMEM_SZ);

    wprep_kernel<<<512, 256>>>(W);
    bias_kernel<<<512, 256>>>(h0, W, bb);

    dim3 grid(4, M_ / 128);

    // layer 0
    aprep_kernel<<<16384, 256>>>(inputs, B_ * D_);
    gemm_kernel<<<grid, 256, SMEM_SZ>>>(c0, 0, hn, cn, nullptr);
    // layer 1 (A = layer-0 h, read from d_out)
    aprep_kernel<<<16384, 256>>>(hn, L_ * B_ * H_);
    gemm_kernel<<<grid, 256, SMEM_SZ>>>(c0, 1, hn, cn, x_out);
}